// round 8
// baseline (speedup 1.0000x reference)
#include <cuda_runtime.h>

#define EPSV 1e-6f

typedef unsigned long long u64;

__device__ __forceinline__ u64 pack2(float x, float y){
    u64 r; asm("mov.b64 %0, {%1, %2};" : "=l"(r) : "f"(x), "f"(y)); return r;
}
__device__ __forceinline__ u64 ffma2(u64 a, u64 b, u64 c){
    u64 d; asm("fma.rn.f32x2 %0, %1, %2, %3;" : "=l"(d) : "l"(a), "l"(b), "l"(c)); return d;
}
__device__ __forceinline__ float2 unpack2(u64 a){
    float2 f; asm("mov.b64 {%0, %1}, %2;" : "=f"(f.x), "=f"(f.y) : "l"(a)); return f;
}

#define BB 8
#define HH 256
#define WW 256
#define CC 64
#define HID 128
#define OC1 256
#define NPIX (BB*HH*WW)
#define PXT 128                 // pixels per GEMM block
#define AST 132                 // act tile row stride (floats): 128 + 4, 16B-aligned

// Scratch (static __device__ globals per harness rules)
__device__ float g_t1[(size_t)NPIX * OC1];   // pw1 output
__device__ float g_y [(size_t)NPIX * HID];   // gated dw output; later reused for k4b1 gate output
__device__ float g_x2[(size_t)NPIX * CC];    // stage-1 residual output
__device__ float g_part[BB * 1024 * HID];    // GAP partials per block
__device__ float g_attn[BB * HID];           // channel attention

// One register-tile GEMM step: 4 px (a4) x 8 outs (w0,w1 as 4 f32-pairs), 16 FFMA2.
#define GEMM_STEP(aPtr, wPtr) do { \
    float4 a4 = *(const float4*)(aPtr); \
    const ulonglong2* wr_ = (const ulonglong2*)(wPtr); \
    ulonglong2 w0 = wr_[0], w1 = wr_[1]; \
    u64 a0 = pack2(a4.x, a4.x), a1 = pack2(a4.y, a4.y); \
    u64 a2 = pack2(a4.z, a4.z), a3 = pack2(a4.w, a4.w); \
    acc[ 0]=ffma2(a0,w0.x,acc[ 0]); acc[ 1]=ffma2(a0,w0.y,acc[ 1]); acc[ 2]=ffma2(a0,w1.x,acc[ 2]); acc[ 3]=ffma2(a0,w1.y,acc[ 3]); \
    acc[ 4]=ffma2(a1,w0.x,acc[ 4]); acc[ 5]=ffma2(a1,w0.y,acc[ 5]); acc[ 6]=ffma2(a1,w1.x,acc[ 6]); acc[ 7]=ffma2(a1,w1.y,acc[ 7]); \
    acc[ 8]=ffma2(a2,w0.x,acc[ 8]); acc[ 9]=ffma2(a2,w0.y,acc[ 9]); acc[10]=ffma2(a2,w1.x,acc[10]); acc[11]=ffma2(a2,w1.y,acc[11]); \
    acc[12]=ffma2(a3,w0.x,acc[12]); acc[13]=ffma2(a3,w0.y,acc[13]); acc[14]=ffma2(a3,w1.x,acc[14]); acc[15]=ffma2(a3,w1.y,acc[15]); \
} while(0)

// ---------------------------------------------------------------------------
// K1: LayerNorm1 + pw1 (64 -> 256), tiled GEMM. 128 px/block, 256 threads.
// thread tile: 4 px x 8 outs; outer loop over 4 output chunks of 64.
// ---------------------------------------------------------------------------
__global__ void __launch_bounds__(256) k1_ln_pw1(
    const float* __restrict__ x, const float* __restrict__ g1,
    const float* __restrict__ b1, const float* __restrict__ W,
    const float* __restrict__ bias)
{
    extern __shared__ float sm[];
    float* sW  = sm;                 // 64*256 = 16384
    float* aT  = sm + 16384;         // 64*AST = 8448 (transposed LN tile)
    float* sB  = aT + 64*AST;        // 256
    float* sG  = sB + 256;           // 64
    float* sBe = sG + 64;            // 64
    int tid = threadIdx.x;
    #pragma unroll 4
    for (int i = tid; i < 16384; i += 256) sW[i] = W[i];
    sB[tid] = bias[tid];
    if (tid < 64) { sG[tid] = g1[tid]; sBe[tid] = b1[tid]; }
    __syncthreads();

    size_t p0 = (size_t)blockIdx.x * PXT;
    // LN: 2 threads per pixel, 32 channels each
    {
        int px = tid >> 1, half = tid & 1;
        const float4* xp = (const float4*)(x + (p0 + px) * 64 + half * 32);
        float4 v[8];
        #pragma unroll
        for (int q = 0; q < 8; q++) v[q] = xp[q];
        float s = 0.f, ss = 0.f;
        #pragma unroll
        for (int q = 0; q < 8; q++){
            float4 t = v[q];
            s += t.x + t.y + t.z + t.w;
            ss = fmaf(t.x,t.x, fmaf(t.y,t.y, fmaf(t.z,t.z, fmaf(t.w,t.w, ss))));
        }
        s  += __shfl_xor_sync(0xffffffffu, s, 1);
        ss += __shfl_xor_sync(0xffffffffu, ss, 1);
        float mean = s * (1.f/64.f);
        float var  = fmaf(-mean, mean, ss * (1.f/64.f));
        float rstd = rsqrtf(var + EPSV);
        #pragma unroll
        for (int q = 0; q < 8; q++){
            float4 t = v[q];
            int ch = half*32 + 4*q;
            aT[(ch+0)*AST + px] = fmaf((t.x-mean)*rstd, sG[ch+0], sBe[ch+0]);
            aT[(ch+1)*AST + px] = fmaf((t.y-mean)*rstd, sG[ch+1], sBe[ch+1]);
            aT[(ch+2)*AST + px] = fmaf((t.z-mean)*rstd, sG[ch+2], sBe[ch+2]);
            aT[(ch+3)*AST + px] = fmaf((t.w-mean)*rstd, sG[ch+3], sBe[ch+3]);
        }
    }
    __syncthreads();

    int ip = tid & 31, jo = tid >> 5;       // warp: same jo, ip = lane
    const float* aBase = aT + ip * 4;
    float* outBase = g_t1 + (p0 + ip * 4) * 256;
    #pragma unroll 1
    for (int oc = 0; oc < 256; oc += 64){
        int ob = oc + jo * 8;
        u64 acc[16];
        const u64* bb = (const u64*)(sB + ob);
        #pragma unroll
        for (int p = 0; p < 4; p++){
            acc[4*p+0]=bb[0]; acc[4*p+1]=bb[1]; acc[4*p+2]=bb[2]; acc[4*p+3]=bb[3];
        }
        const float* wBase = sW + ob;
        #pragma unroll 8
        for (int k = 0; k < 64; k++){
            GEMM_STEP(aBase + k*AST, wBase + k*256);
        }
        #pragma unroll
        for (int p = 0; p < 4; p++){
            float2 r0 = unpack2(acc[4*p+0]), r1 = unpack2(acc[4*p+1]);
            float2 r2 = unpack2(acc[4*p+2]), r3 = unpack2(acc[4*p+3]);
            float4* op = (float4*)(outBase + (size_t)p*256 + ob);
            op[0] = make_float4(r0.x, r0.y, r1.x, r1.y);
            op[1] = make_float4(r2.x, r2.y, r3.x, r3.y);
        }
    }
}

// ---------------------------------------------------------------------------
// K2: depthwise 3x3 (SAME) + SimpleGate + GAP partials (unchanged)
// ---------------------------------------------------------------------------
__global__ void k2_dw_gate(const float* __restrict__ dww, const float* __restrict__ dwb)
{
    int blk = blockIdx.x;           // b*1024 + h*4 + wt
    int b   = blk >> 10;
    int rem = blk & 1023;
    int h   = rem >> 2;
    int w0  = (rem & 3) << 6;
    int c   = threadIdx.x;          // 0..127
    int c2  = c + 128;
    float wt0[9], wt1[9];
    #pragma unroll
    for (int i = 0; i < 9; i++){ wt0[i] = dww[i*256 + c]; wt1[i] = dww[i*256 + c2]; }
    float bc0 = dwb[c], bc1 = dwb[c2];

    const float* img = g_t1 + (size_t)b * HH * WW * 256;
    bool v0 = (h > 0), v2 = (h < HH-1);
    const float* r0 = img + (size_t)(h-1) * WW * 256;
    const float* r1 = img + (size_t)h     * WW * 256;
    const float* r2 = img + (size_t)(h+1) * WW * 256;

    float win0[9], win1[9];
    {
        int wm = w0 - 1;
        bool vm = (wm >= 0);
        win0[0] = (v0 && vm) ? r0[(size_t)wm*256 + c ] : 0.f;
        win0[3] =  vm        ? r1[(size_t)wm*256 + c ] : 0.f;
        win0[6] = (v2 && vm) ? r2[(size_t)wm*256 + c ] : 0.f;
        win1[0] = (v0 && vm) ? r0[(size_t)wm*256 + c2] : 0.f;
        win1[3] =  vm        ? r1[(size_t)wm*256 + c2] : 0.f;
        win1[6] = (v2 && vm) ? r2[(size_t)wm*256 + c2] : 0.f;
        win0[1] = v0 ? r0[(size_t)w0*256 + c ] : 0.f;
        win0[4] =      r1[(size_t)w0*256 + c ];
        win0[7] = v2 ? r2[(size_t)w0*256 + c ] : 0.f;
        win1[1] = v0 ? r0[(size_t)w0*256 + c2] : 0.f;
        win1[4] =      r1[(size_t)w0*256 + c2];
        win1[7] = v2 ? r2[(size_t)w0*256 + c2] : 0.f;
    }
    float* yrow = g_y + ((size_t)(b*HH + h) * WW) * 128;
    float gap = 0.f;
    for (int w = w0; w < w0 + 64; w++){
        int wp = w + 1;
        bool vp = (wp < WW);
        win0[2] = (v0 && vp) ? r0[(size_t)wp*256 + c ] : 0.f;
        win0[5] =  vp        ? r1[(size_t)wp*256 + c ] : 0.f;
        win0[8] = (v2 && vp) ? r2[(size_t)wp*256 + c ] : 0.f;
        win1[2] = (v0 && vp) ? r0[(size_t)wp*256 + c2] : 0.f;
        win1[5] =  vp        ? r1[(size_t)wp*256 + c2] : 0.f;
        win1[8] = (v2 && vp) ? r2[(size_t)wp*256 + c2] : 0.f;
        float a = bc0, bbv = bc1;
        #pragma unroll
        for (int i = 0; i < 9; i++){ a = fmaf(win0[i], wt0[i], a); bbv = fmaf(win1[i], wt1[i], bbv); }
        float yv = a * bbv;
        yrow[(size_t)w * 128 + c] = yv;
        gap += yv;
        #pragma unroll
        for (int r = 0; r < 3; r++){
            win0[r*3+0] = win0[r*3+1]; win0[r*3+1] = win0[r*3+2];
            win1[r*3+0] = win1[r*3+1]; win1[r*3+1] = win1[r*3+2];
        }
    }
    g_part[(size_t)blk * 128 + c] = gap;
}

// ---------------------------------------------------------------------------
// K3: GAP reduce + SCA (unchanged)
// ---------------------------------------------------------------------------
__global__ void k3_sca(const float* __restrict__ scaw, const float* __restrict__ scab)
{
    __shared__ float smn[128];
    int b = blockIdx.x, c = threadIdx.x;
    const float* p = g_part + (size_t)b * 1024 * 128 + c;
    float s = 0.f;
    #pragma unroll 8
    for (int i = 0; i < 1024; i++) s += p[(size_t)i * 128];
    smn[c] = s * (1.f / 65536.f);
    __syncthreads();
    float a = scab[c];
    #pragma unroll 8
    for (int k = 0; k < 128; k++) a = fmaf(smn[k], scaw[k*128 + c], a);
    g_attn[b*128 + c] = a;
}

// ---------------------------------------------------------------------------
// K4a: (y*attn) -> pw2 (128 -> 64) -> x2 = x + .*beta, tiled GEMM.
// 128 px/block, K chunked by 32. thread tile: 4 px x 8 outs.
// ---------------------------------------------------------------------------
__global__ void __launch_bounds__(256) k4a_att_pw2(
    const float* __restrict__ x, const float* __restrict__ W2,
    const float* __restrict__ b2, const float* __restrict__ beta)
{
    extern __shared__ float sm[];
    float* sW    = sm;              // 128*64 = 8192
    float* aT    = sm + 8192;       // 32*AST = 4224
    float* sA    = aT + 32*AST;     // 128
    float* sB2   = sA + 128;        // 64
    float* sBeta = sB2 + 64;        // 64
    int tid = threadIdx.x;
    int b = blockIdx.x >> 9;        // 512 blocks per image
    #pragma unroll 4
    for (int i = tid; i < 8192; i += 256) sW[i] = W2[i];
    if (tid < 128) sA[tid] = g_attn[b*128 + tid];
    else if (tid < 192) sB2[tid-128] = b2[tid-128];
    else sBeta[tid-192] = beta[tid-192];
    __syncthreads();

    size_t p0 = (size_t)blockIdx.x * PXT;
    int ip = tid & 31, jo = tid >> 5;
    int ob = jo * 8;
    u64 acc[16];
    {
        const u64* bb = (const u64*)(sB2 + ob);
        #pragma unroll
        for (int p = 0; p < 4; p++){
            acc[4*p+0]=bb[0]; acc[4*p+1]=bb[1]; acc[4*p+2]=bb[2]; acc[4*p+3]=bb[3];
        }
    }
    int lpx = tid >> 1, lco = (tid & 1) * 16;
    const float4* yp = (const float4*)(g_y + (p0 + lpx) * 128 + lco);
    const float* aBase = aT + ip * 4;
    #pragma unroll 1
    for (int kc = 0; kc < 128; kc += 32){
        // stage chunk: y * attn, transposed
        #pragma unroll
        for (int q = 0; q < 4; q++){
            float4 yv = yp[(kc >> 2) + q];
            int ch = lco + 4*q;
            aT[(ch+0)*AST + lpx] = yv.x * sA[kc+ch+0];
            aT[(ch+1)*AST + lpx] = yv.y * sA[kc+ch+1];
            aT[(ch+2)*AST + lpx] = yv.z * sA[kc+ch+2];
            aT[(ch+3)*AST + lpx] = yv.w * sA[kc+ch+3];
        }
        __syncthreads();
        const float* wBase = sW + kc*64 + ob;
        #pragma unroll 8
        for (int k = 0; k < 32; k++){
            GEMM_STEP(aBase + k*AST, wBase + k*64);
        }
        __syncthreads();
    }
    // epilogue: x + acc*beta -> g_x2
    #pragma unroll
    for (int p = 0; p < 4; p++){
        size_t px = p0 + ip*4 + p;
        const float4* xq = (const float4*)(x + px*64 + ob);
        float4 x0 = xq[0], x1 = xq[1];
        float2 r0 = unpack2(acc[4*p+0]), r1 = unpack2(acc[4*p+1]);
        float2 r2 = unpack2(acc[4*p+2]), r3 = unpack2(acc[4*p+3]);
        float4 o0, o1;
        o0.x = fmaf(r0.x, sBeta[ob+0], x0.x); o0.y = fmaf(r0.y, sBeta[ob+1], x0.y);
        o0.z = fmaf(r1.x, sBeta[ob+2], x0.z); o0.w = fmaf(r1.y, sBeta[ob+3], x0.w);
        o1.x = fmaf(r2.x, sBeta[ob+4], x1.x); o1.y = fmaf(r2.y, sBeta[ob+5], x1.y);
        o1.z = fmaf(r3.x, sBeta[ob+6], x1.z); o1.w = fmaf(r3.y, sBeta[ob+7], x1.w);
        float4* op = (float4*)(g_x2 + px*64 + ob);
        op[0] = o0; op[1] = o1;
    }
}

// ---------------------------------------------------------------------------
// K4b1: LN2 -> pw3 (64 -> 256, pair-interleaved) -> SimpleGate -> g (into g_y)
// Same tiling as k1; epilogue multiplies pairs within each f32x2 accumulator.
// ---------------------------------------------------------------------------
__global__ void __launch_bounds__(256) k4b1_ln_pw3(
    const float* __restrict__ W3, const float* __restrict__ b3,
    const float* __restrict__ g2, const float* __restrict__ bb2)
{
    extern __shared__ float sm[];
    float* sW  = sm;                 // 16384 (interleaved pairs)
    float* aT  = sm + 16384;         // 64*AST = 8448
    float* sB  = aT + 64*AST;        // 256 (interleaved)
    float* sG  = sB + 256;           // 64
    float* sBe = sG + 64;            // 64
    int tid = threadIdx.x;
    for (int i = tid; i < 16384; i += 256){
        int k = i >> 8, t = i & 255, j = t >> 1, h = t & 1;
        sW[i] = W3[k*256 + h*128 + j];
    }
    sB[tid] = b3[((tid & 1) * 128) + (tid >> 1)];
    if (tid < 64) { sG[tid] = g2[tid]; sBe[tid] = bb2[tid]; }
    __syncthreads();

    size_t p0 = (size_t)blockIdx.x * PXT;
    {
        int px = tid >> 1, half = tid & 1;
        const float4* xp = (const float4*)(g_x2 + (p0 + px) * 64 + half * 32);
        float4 v[8];
        #pragma unroll
        for (int q = 0; q < 8; q++) v[q] = xp[q];
        float s = 0.f, ss = 0.f;
        #pragma unroll
        for (int q = 0; q < 8; q++){
            float4 t = v[q];
            s += t.x + t.y + t.z + t.w;
            ss = fmaf(t.x,t.x, fmaf(t.y,t.y, fmaf(t.z,t.z, fmaf(t.w,t.w, ss))));
        }
        s  += __shfl_xor_sync(0xffffffffu, s, 1);
        ss += __shfl_xor_sync(0xffffffffu, ss, 1);
        float mean = s * (1.f/64.f);
        float var  = fmaf(-mean, mean, ss * (1.f/64.f));
        float rstd = rsqrtf(var + EPSV);
        #pragma unroll
        for (int q = 0; q < 8; q++){
            float4 t = v[q];
            int ch = half*32 + 4*q;
            aT[(ch+0)*AST + px] = fmaf((t.x-mean)*rstd, sG[ch+0], sBe[ch+0]);
            aT[(ch+1)*AST + px] = fmaf((t.y-mean)*rstd, sG[ch+1], sBe[ch+1]);
            aT[(ch+2)*AST + px] = fmaf((t.z-mean)*rstd, sG[ch+2], sBe[ch+2]);
            aT[(ch+3)*AST + px] = fmaf((t.w-mean)*rstd, sG[ch+3], sBe[ch+3]);
        }
    }
    __syncthreads();

    int ip = tid & 31, jo = tid >> 5;
    const float* aBase = aT + ip * 4;
    #pragma unroll 1
    for (int oc = 0; oc < 256; oc += 64){
        int ob = oc + jo * 8;
        u64 acc[16];
        const u64* bb = (const u64*)(sB + ob);
        #pragma unroll
        for (int p = 0; p < 4; p++){
            acc[4*p+0]=bb[0]; acc[4*p+1]=bb[1]; acc[4*p+2]=bb[2]; acc[4*p+3]=bb[3];
        }
        const float* wBase = sW + ob;
        #pragma unroll 8
        for (int k = 0; k < 64; k++){
            GEMM_STEP(aBase + k*AST, wBase + k*256);
        }
        // gate: product of pair within each u64 -> 4 floats per px
        int gb = (oc >> 1) + jo * 4;
        #pragma unroll
        for (int p = 0; p < 4; p++){
            float2 r0 = unpack2(acc[4*p+0]), r1 = unpack2(acc[4*p+1]);
            float2 r2 = unpack2(acc[4*p+2]), r3 = unpack2(acc[4*p+3]);
            float4 g4 = make_float4(r0.x*r0.y, r1.x*r1.y, r2.x*r2.y, r3.x*r3.y);
            *(float4*)(g_y + (p0 + ip*4 + p) * 128 + gb) = g4;
        }
    }
}

// ---------------------------------------------------------------------------
// K4b2: pw4 (128 -> 64) -> out = x2 + .*gamma, tiled GEMM (k4a without attn)
// ---------------------------------------------------------------------------
__global__ void __launch_bounds__(256) k4b2_pw4(
    const float* __restrict__ W4, const float* __restrict__ b4,
    const float* __restrict__ gamma, float* __restrict__ out)
{
    extern __shared__ float sm[];
    float* sW  = sm;               // 8192
    float* aT  = sm + 8192;        // 32*AST = 4224
    float* sB4 = aT + 32*AST;      // 64
    float* sGa = sB4 + 64;         // 64
    int tid = threadIdx.x;
    #pragma unroll 4
    for (int i = tid; i < 8192; i += 256) sW[i] = W4[i];
    if (tid < 64) sB4[tid] = b4[tid];
    else if (tid < 128) sGa[tid-64] = gamma[tid-64];
    __syncthreads();

    size_t p0 = (size_t)blockIdx.x * PXT;
    int ip = tid & 31, jo = tid >> 5;
    int ob = jo * 8;
    u64 acc[16];
    {
        const u64* bb = (const u64*)(sB4 + ob);
        #pragma unroll
        for (int p = 0; p < 4; p++){
            acc[4*p+0]=bb[0]; acc[4*p+1]=bb[1]; acc[4*p+2]=bb[2]; acc[4*p+3]=bb[3];
        }
    }
    int lpx = tid >> 1, lco = (tid & 1) * 16;
    const float4* yp = (const float4*)(g_y + (p0 + lpx) * 128 + lco);
    const float* aBase = aT + ip * 4;
    #pragma unroll 1
    for (int kc = 0; kc < 128; kc += 32){
        #pragma unroll
        for (int q = 0; q < 4; q++){
            float4 yv = yp[(kc >> 2) + q];
            int ch = lco + 4*q;
            aT[(ch+0)*AST + lpx] = yv.x;
            aT[(ch+1)*AST + lpx] = yv.y;
            aT[(ch+2)*AST + lpx] = yv.z;
            aT[(ch+3)*AST + lpx] = yv.w;
        }
        __syncthreads();
        const float* wBase = sW + kc*64 + ob;
        #pragma unroll 8
        for (int k = 0; k < 32; k++){
            GEMM_STEP(aBase + k*AST, wBase + k*64);
        }
        __syncthreads();
    }
    #pragma unroll
    for (int p = 0; p < 4; p++){
        size_t px = p0 + ip*4 + p;
        const float4* xq = (const float4*)(g_x2 + px*64 + ob);
        float4 x0 = xq[0], x1 = xq[1];
        float2 r0 = unpack2(acc[4*p+0]), r1 = unpack2(acc[4*p+1]);
        float2 r2 = unpack2(acc[4*p+2]), r3 = unpack2(acc[4*p+3]);
        float4 o0, o1;
        o0.x = fmaf(r0.x, sGa[ob+0], x0.x); o0.y = fmaf(r0.y, sGa[ob+1], x0.y);
        o0.z = fmaf(r1.x, sGa[ob+2], x0.z); o0.w = fmaf(r1.y, sGa[ob+3], x0.w);
        o1.x = fmaf(r2.x, sGa[ob+4], x1.x); o1.y = fmaf(r2.y, sGa[ob+5], x1.y);
        o1.z = fmaf(r3.x, sGa[ob+6], x1.z); o1.w = fmaf(r3.y, sGa[ob+7], x1.w);
        float4* op = (float4*)(out + px*64 + ob);
        op[0] = o0; op[1] = o1;
    }
}

// ---------------------------------------------------------------------------
extern "C" void kernel_launch(void* const* d_in, const int* in_sizes, int n_in,
                              void* d_out, int out_size)
{
    const float* x    = (const float*)d_in[0];
    const float* ln1g = (const float*)d_in[1];
    const float* ln1b = (const float*)d_in[2];
    const float* pw1w = (const float*)d_in[3];
    const float* pw1b = (const float*)d_in[4];
    const float* dww  = (const float*)d_in[5];
    const float* dwb  = (const float*)d_in[6];
    const float* scaw = (const float*)d_in[7];
    const float* scab = (const float*)d_in[8];
    const float* pw2w = (const float*)d_in[9];
    const float* pw2b = (const float*)d_in[10];
    const float* beta = (const float*)d_in[11];
    const float* ln2g = (const float*)d_in[12];
    const float* ln2b = (const float*)d_in[13];
    const float* pw3w = (const float*)d_in[14];
    const float* pw3b = (const float*)d_in[15];
    const float* pw4w = (const float*)d_in[16];
    const float* pw4b = (const float*)d_in[17];
    const float* gam  = (const float*)d_in[18];
    float* out = (float*)d_out;

    int smem_k1   = (16384 + 64*AST + 256 + 64 + 64) * 4;            // 100864
    int smem_k4a  = (8192 + 32*AST + 128 + 64 + 64) * 4;             // 50688
    int smem_k4b1 = smem_k1;
    int smem_k4b2 = (8192 + 32*AST + 64 + 64) * 4;                   // 50176
    cudaFuncSetAttribute(k1_ln_pw1,  cudaFuncAttributeMaxDynamicSharedMemorySize, smem_k1);
    cudaFuncSetAttribute(k4a_att_pw2, cudaFuncAttributeMaxDynamicSharedMemorySize, smem_k4a);
    cudaFuncSetAttribute(k4b1_ln_pw3, cudaFuncAttributeMaxDynamicSharedMemorySize, smem_k4b1);
    cudaFuncSetAttribute(k4b2_pw4,   cudaFuncAttributeMaxDynamicSharedMemorySize, smem_k4b2);

    k1_ln_pw1  <<<NPIX/PXT, 256, smem_k1>>>(x, ln1g, ln1b, pw1w, pw1b);
    k2_dw_gate <<<BB*1024, 128>>>(dww, dwb);
    k3_sca     <<<BB, 128>>>(scaw, scab);
    k4a_att_pw2<<<NPIX/PXT, 256, smem_k4a>>>(x, pw2w, pw2b, beta);
    k4b1_ln_pw3<<<NPIX/PXT, 256, smem_k4b1>>>(pw3w, pw3b, ln2g, ln2b);
    k4b2_pw4   <<<NPIX/PXT, 256, smem_k4b2>>>(pw4w, pw4b, gam, out);
}

// round 10
// speedup vs baseline: 1.7989x; 1.7989x over previous
#include <cuda_runtime.h>
#include <cuda_bf16.h>
#include <cstdint>

#define EPSV 1e-6f

#define BB 8
#define HH 256
#define WW 256
#define CC 64
#define NPIX (BB*HH*WW)

// ---------------------------------------------------------------------------
// Scratch (static __device__ globals per harness rules)
// ---------------------------------------------------------------------------
__device__ __nv_bfloat16 g_t1b[(size_t)NPIX * 256];  // pw1 output (bf16)
__device__ __nv_bfloat16 g_yb [(size_t)NPIX * 128];  // gated dw out / stage-2 gate (bf16)
__device__ float g_x2[(size_t)NPIX * CC];            // stage-1 residual (fp32)
__device__ float g_part[BB * 1024 * 128];            // GAP partials
__device__ float g_attn[BB * 128];                   // channel attention
// Transposed bf16 weights (n-major rows, k contiguous)
__device__ __align__(16) __nv_bfloat16 g_w1t[256*64];
__device__ __align__(16) __nv_bfloat16 g_w2t[64*128];
__device__ __align__(16) __nv_bfloat16 g_w3t[256*64];   // gate-interleaved rows
__device__ __align__(16) __nv_bfloat16 g_w4t[64*128];

// ---------------------------------------------------------------------------
// Helpers
// ---------------------------------------------------------------------------
__device__ __forceinline__ uint32_t smem_u32(const void* p){
    uint32_t a; asm("{ .reg .u64 t; cvta.to.shared.u64 t, %1; cvt.u32.u64 %0, t; }" : "=r"(a) : "l"(p)); return a;
}
__device__ __forceinline__ void ldsm4(uint32_t* r, uint32_t addr){
    asm volatile("ldmatrix.sync.aligned.m8n8.x4.shared.b16 {%0,%1,%2,%3}, [%4];"
        : "=r"(r[0]), "=r"(r[1]), "=r"(r[2]), "=r"(r[3]) : "r"(addr));
}
__device__ __forceinline__ void ldsm2(uint32_t* r, uint32_t addr){
    asm volatile("ldmatrix.sync.aligned.m8n8.x2.shared.b16 {%0,%1}, [%2];"
        : "=r"(r[0]), "=r"(r[1]) : "r"(addr));
}
__device__ __forceinline__ void mma16816(float* d, const uint32_t* a, const uint32_t* b){
    asm volatile("mma.sync.aligned.m16n8k16.row.col.f32.bf16.bf16.f32 "
        "{%0,%1,%2,%3}, {%4,%5,%6,%7}, {%8,%9}, {%0,%1,%2,%3};"
        : "+f"(d[0]), "+f"(d[1]), "+f"(d[2]), "+f"(d[3])
        : "r"(a[0]), "r"(a[1]), "r"(a[2]), "r"(a[3]), "r"(b[0]), "r"(b[1]));
}
__device__ __forceinline__ uint32_t bfpack(float a, float b){
    __nv_bfloat162 h = __floats2bfloat162_rn(a, b);
    return *(uint32_t*)&h;
}
__device__ __forceinline__ float2 bfunpk(uint32_t u){
    __nv_bfloat162 h = *(__nv_bfloat162*)&u;
    return __bfloat1622float2(h);
}
__device__ __forceinline__ void st_bf2(__nv_bfloat16* p, float a, float b){
    *(__nv_bfloat162*)p = __floats2bfloat162_rn(a, b);
}

// ---------------------------------------------------------------------------
// K0: weight prep — transposed bf16 (n-major)
// ---------------------------------------------------------------------------
__global__ void k0_prep(const float* __restrict__ w1, const float* __restrict__ w2,
                        const float* __restrict__ w3, const float* __restrict__ w4)
{
    int idx = blockIdx.x * 256 + threadIdx.x;     // 192*256 = 49152
    if (idx < 16384){                             // w1t [256 n][64 k]
        int n = idx >> 6, k = idx & 63;
        g_w1t[n*64 + k] = __float2bfloat16(w1[k*256 + n]);
    } else if (idx < 24576){                      // w2t [64 n][128 k]
        int i = idx - 16384; int n = i >> 7, k = i & 127;
        g_w2t[n*128 + k] = __float2bfloat16(w2[k*64 + n]);
    } else if (idx < 40960){                      // w3t interleaved [256 n][64 k]
        int i = idx - 24576; int n = i >> 6, k = i & 63;
        g_w3t[n*64 + k] = __float2bfloat16(w3[k*256 + (n & 1)*128 + (n >> 1)]);
    } else {                                      // w4t [64 n][128 k]
        int i = idx - 40960; int n = i >> 7, k = i & 127;
        g_w4t[n*128 + k] = __float2bfloat16(w4[k*64 + n]);
    }
}

// ---------------------------------------------------------------------------
// K1: LN1 + pw1 (64 -> 256) via mma.sync. 128 px/block, 256 threads (8 warps).
// smem: sA [128 x 72 bf16] (144B rows), sW [256 x 72 bf16], bias, g, be
// ---------------------------------------------------------------------------
#define K1_SW_OFF   18432
#define K1_PAR_OFF  55296
#define K1_SMEM     56832

__global__ void __launch_bounds__(256) k1_ln_pw1(
    const float* __restrict__ x, const float* __restrict__ g1,
    const float* __restrict__ b1v, const float* __restrict__ bias)
{
    extern __shared__ char smem[];
    uint32_t sb = smem_u32(smem);
    int tid = threadIdx.x, wid = tid >> 5, lane = tid & 31;
    float* sBias = (float*)(smem + K1_PAR_OFF);   // 256
    float* sG  = sBias + 256;                     // 64
    float* sBe = sG + 64;                         // 64

    // weights: thread t copies row t (64 bf16 = 8 uint4)
    {
        const uint4* src = (const uint4*)(g_w1t + tid*64);
        uint4* dst = (uint4*)(smem + K1_SW_OFF + tid*144);
        #pragma unroll
        for (int q = 0; q < 8; q++) dst[q] = src[q];
    }
    sBias[tid] = bias[tid];
    if (tid < 64){ sG[tid] = g1[tid]; sBe[tid] = b1v[tid]; }
    __syncthreads();

    size_t P0 = (size_t)blockIdx.x * 128;
    {   // LN: 2 threads per pixel, 32 ch each; write bf16 into padded sA
        int px = tid >> 1, half = tid & 1;
        const float4* xp = (const float4*)(x + (P0 + px) * 64 + half * 32);
        float4 v[8];
        #pragma unroll
        for (int q = 0; q < 8; q++) v[q] = xp[q];
        float s = 0.f, ss = 0.f;
        #pragma unroll
        for (int q = 0; q < 8; q++){
            float4 t = v[q];
            s += t.x + t.y + t.z + t.w;
            ss = fmaf(t.x,t.x, fmaf(t.y,t.y, fmaf(t.z,t.z, fmaf(t.w,t.w, ss))));
        }
        s  += __shfl_xor_sync(0xffffffffu, s, 1);
        ss += __shfl_xor_sync(0xffffffffu, ss, 1);
        float mean = s * (1.f/64.f);
        float var  = fmaf(-mean, mean, ss * (1.f/64.f));
        float rstd = rsqrtf(var + EPSV);
        char* dstrow = smem + px*144 + half*64;
        #pragma unroll
        for (int g = 0; g < 4; g++){
            float4 va = v[2*g], vb = v[2*g+1];
            int c = half*32 + g*8;
            float f0 = fmaf((va.x-mean)*rstd, sG[c+0], sBe[c+0]);
            float f1 = fmaf((va.y-mean)*rstd, sG[c+1], sBe[c+1]);
            float f2 = fmaf((va.z-mean)*rstd, sG[c+2], sBe[c+2]);
            float f3 = fmaf((va.w-mean)*rstd, sG[c+3], sBe[c+3]);
            float f4 = fmaf((vb.x-mean)*rstd, sG[c+4], sBe[c+4]);
            float f5 = fmaf((vb.y-mean)*rstd, sG[c+5], sBe[c+5]);
            float f6 = fmaf((vb.z-mean)*rstd, sG[c+6], sBe[c+6]);
            float f7 = fmaf((vb.w-mean)*rstd, sG[c+7], sBe[c+7]);
            *(uint4*)(dstrow + g*16) = make_uint4(bfpack(f0,f1), bfpack(f2,f3),
                                                  bfpack(f4,f5), bfpack(f6,f7));
        }
    }
    __syncthreads();

    // GEMM: warp n-slice = 32
    int ns = wid * 32;
    int br = lane & 7, bg = (lane >> 3) & 1;
    uint32_t bfr[4][4][2];
    #pragma unroll
    for (int nt = 0; nt < 4; nt++)
        #pragma unroll
        for (int kt = 0; kt < 4; kt++)
            ldsm2(bfr[nt][kt], sb + K1_SW_OFF + (ns + nt*8 + br)*144 + bg*16 + kt*32);

    int ag = lane >> 3, ar = lane & 7;
    uint32_t abase = sb + (ar + (ag & 1)*8)*144 + (ag >> 1)*16;
    #pragma unroll 1
    for (int mt = 0; mt < 8; mt++){
        uint32_t af[4][4];
        #pragma unroll
        for (int kt = 0; kt < 4; kt++) ldsm4(af[kt], abase + mt*2304 + kt*32);
        float acc[4][4];
        #pragma unroll
        for (int nt = 0; nt < 4; nt++){ acc[nt][0]=0.f; acc[nt][1]=0.f; acc[nt][2]=0.f; acc[nt][3]=0.f; }
        #pragma unroll
        for (int kt = 0; kt < 4; kt++)
            #pragma unroll
            for (int nt = 0; nt < 4; nt++)
                mma16816(acc[nt], af[kt], bfr[nt][kt]);
        int r0 = mt*16 + (lane >> 2);
        int c0 = ns + (lane & 3)*2;
        __nv_bfloat16* o0 = g_t1b + (P0 + r0)*256;
        __nv_bfloat16* o1 = o0 + 8*256;
        #pragma unroll
        for (int nt = 0; nt < 4; nt++){
            int c = c0 + nt*8;
            st_bf2(o0 + c, acc[nt][0] + sBias[c], acc[nt][1] + sBias[c+1]);
            st_bf2(o1 + c, acc[nt][2] + sBias[c], acc[nt][3] + sBias[c+1]);
        }
    }
}

// ---------------------------------------------------------------------------
// K2: depthwise 3x3 + SimpleGate + GAP partials (bf16 I/O)
// ---------------------------------------------------------------------------
__global__ void __launch_bounds__(128) k2_dw_gate(const float* __restrict__ dww, const float* __restrict__ dwb)
{
    int blk = blockIdx.x;            // b*512 + h*2 + wseg
    int b   = blk >> 9;
    int rem = blk & 511;
    int h   = rem >> 1;
    int wseg= rem & 1;
    int sub = threadIdx.x >> 6;
    int c2  = threadIdx.x & 63;
    int ch  = c2 * 2;
    int w0  = wseg*128 + sub*64;

    float2 wt0[9], wt1[9];
    #pragma unroll
    for (int i = 0; i < 9; i++){
        wt0[i] = make_float2(dww[i*256 + ch],       dww[i*256 + ch + 1]);
        wt1[i] = make_float2(dww[i*256 + 128 + ch], dww[i*256 + 128 + ch + 1]);
    }
    float2 bc0 = make_float2(dwb[ch], dwb[ch+1]);
    float2 bc1 = make_float2(dwb[128+ch], dwb[128+ch+1]);

    const __nv_bfloat162* img = (const __nv_bfloat162*)g_t1b;
    size_t rowb = (size_t)(b*256 + h) * 256;
    bool v0 = (h > 0), v2 = (h < HH-1);
    #define LD0(rr, wc) __bfloat1622float2(img[((rr) + (size_t)(wc))*128 + c2])
    #define LD1(rr, wc) __bfloat1622float2(img[((rr) + (size_t)(wc))*128 + 64 + c2])
    size_t r0 = rowb - 256, r1 = rowb, r2 = rowb + 256;
    const float2 Z = make_float2(0.f, 0.f);

    float2 win0[9], win1[9];
    {
        int wm = w0 - 1; bool vm = (wm >= 0);
        win0[0] = (v0 && vm) ? LD0(r0, wm) : Z;
        win0[3] =  vm        ? LD0(r1, wm) : Z;
        win0[6] = (v2 && vm) ? LD0(r2, wm) : Z;
        win1[0] = (v0 && vm) ? LD1(r0, wm) : Z;
        win1[3] =  vm        ? LD1(r1, wm) : Z;
        win1[6] = (v2 && vm) ? LD1(r2, wm) : Z;
        win0[1] = v0 ? LD0(r0, w0) : Z;
        win0[4] =      LD0(r1, w0);
        win0[7] = v2 ? LD0(r2, w0) : Z;
        win1[1] = v0 ? LD1(r0, w0) : Z;
        win1[4] =      LD1(r1, w0);
        win1[7] = v2 ? LD1(r2, w0) : Z;
    }
    __nv_bfloat162* yrow = (__nv_bfloat162*)g_yb;
    float2 gap = Z;
    for (int w = w0; w < w0 + 64; w++){
        int wp = w + 1; bool vp = (wp < WW);
        win0[2] = (v0 && vp) ? LD0(r0, wp) : Z;
        win0[5] =  vp        ? LD0(r1, wp) : Z;
        win0[8] = (v2 && vp) ? LD0(r2, wp) : Z;
        win1[2] = (v0 && vp) ? LD1(r0, wp) : Z;
        win1[5] =  vp        ? LD1(r1, wp) : Z;
        win1[8] = (v2 && vp) ? LD1(r2, wp) : Z;
        float2 a = bc0, c = bc1;
        #pragma unroll
        for (int i = 0; i < 9; i++){
            a.x = fmaf(win0[i].x, wt0[i].x, a.x); a.y = fmaf(win0[i].y, wt0[i].y, a.y);
            c.x = fmaf(win1[i].x, wt1[i].x, c.x); c.y = fmaf(win1[i].y, wt1[i].y, c.y);
        }
        float2 yv = make_float2(a.x * c.x, a.y * c.y);
        yrow[(rowb + (size_t)w)*64 + c2] = __floats2bfloat162_rn(yv.x, yv.y);
        gap.x += yv.x; gap.y += yv.y;
        #pragma unroll
        for (int r = 0; r < 3; r++){
            win0[r*3+0] = win0[r*3+1]; win0[r*3+1] = win0[r*3+2];
            win1[r*3+0] = win1[r*3+1]; win1[r*3+1] = win1[r*3+2];
        }
    }
    int pid = blk*2 + sub;
    g_part[(size_t)pid*128 + ch]     = gap.x;
    g_part[(size_t)pid*128 + ch + 1] = gap.y;
    #undef LD0
    #undef LD1
}

// ---------------------------------------------------------------------------
// K3: GAP reduce + SCA
// ---------------------------------------------------------------------------
__global__ void k3_sca(const float* __restrict__ scaw, const float* __restrict__ scab)
{
    __shared__ float smn[128];
    int b = blockIdx.x, c = threadIdx.x;
    const float* p = g_part + (size_t)b * 1024 * 128 + c;
    float s = 0.f;
    #pragma unroll 8
    for (int i = 0; i < 1024; i++) s += p[(size_t)i * 128];
    smn[c] = s * (1.f / 65536.f);
    __syncthreads();
    float a = scab[c];
    #pragma unroll 8
    for (int k = 0; k < 128; k++) a = fmaf(smn[k], scaw[k*128 + c], a);
    g_attn[b*128 + c] = a;
}

// ---------------------------------------------------------------------------
// K4a: (y*attn) -> pw2 (128 -> 64) -> x2 = x + .*beta. mma.sync, warp n-slice 8.
// smem: sA [128 x 136 bf16] (272B rows), sW [64 x 136 bf16], attn, bias, beta
// ---------------------------------------------------------------------------
#define K4A_SW_OFF  34816
#define K4A_PAR_OFF 52224
#define K4A_SMEM    53248

__global__ void __launch_bounds__(256) k4a_att_pw2(
    const float* __restrict__ x, const float* __restrict__ b2v, const float* __restrict__ beta)
{
    extern __shared__ char smem[];
    uint32_t sb = smem_u32(smem);
    int tid = threadIdx.x, wid = tid >> 5, lane = tid & 31;
    float* sAttn = (float*)(smem + K4A_PAR_OFF);  // 128
    float* sB2   = sAttn + 128;                   // 64
    float* sBeta = sB2 + 64;                      // 64
    int b = blockIdx.x >> 9;

    {   // weights: 4 threads per row, 64B each
        int row = tid >> 2, part = tid & 3;
        const uint4* src = (const uint4*)(g_w2t + row*128 + part*32);
        uint4* dst = (uint4*)(smem + K4A_SW_OFF + row*272 + part*64);
        #pragma unroll
        for (int q = 0; q < 4; q++) dst[q] = src[q];
    }
    if (tid < 128) sAttn[tid] = g_attn[b*128 + tid];
    else if (tid < 192) sB2[tid-128] = b2v[tid-128];
    else sBeta[tid-192] = beta[tid-192];
    __syncthreads();

    size_t P0 = (size_t)blockIdx.x * 128;
    {   // stage A = y * attn (bf16, padded rows)
        int row = tid >> 1, half = tid & 1;
        const uint4* src = (const uint4*)(g_yb + (P0 + row)*128 + half*64);
        char* dstrow = smem + row*272 + half*128;
        #pragma unroll
        for (int q = 0; q < 8; q++){
            uint4 raw = src[q];
            const uint32_t* rw = (const uint32_t*)&raw;
            int k0 = half*64 + q*8;
            uint32_t pk[4];
            #pragma unroll
            for (int j = 0; j < 4; j++){
                float2 f = bfunpk(rw[j]);
                f.x *= sAttn[k0 + 2*j]; f.y *= sAttn[k0 + 2*j + 1];
                pk[j] = bfpack(f.x, f.y);
            }
            *(uint4*)(dstrow + q*16) = make_uint4(pk[0], pk[1], pk[2], pk[3]);
        }
    }
    __syncthreads();

    int n0 = wid * 8;
    int br = lane & 7, bg = (lane >> 3) & 1;
    uint32_t bfr[8][2];
    #pragma unroll
    for (int kt = 0; kt < 8; kt++)
        ldsm2(bfr[kt], sb + K4A_SW_OFF + (n0 + br)*272 + bg*16 + kt*32);

    int ag = lane >> 3, ar = lane & 7;
    uint32_t abase = sb + (ar + (ag & 1)*8)*272 + (ag >> 1)*16;
    #pragma unroll 1
    for (int mt = 0; mt < 8; mt++){
        uint32_t af[8][4];
        #pragma unroll
        for (int kt = 0; kt < 8; kt++) ldsm4(af[kt], abase + mt*4352 + kt*32);
        float acc[4] = {0.f, 0.f, 0.f, 0.f};
        #pragma unroll
        for (int kt = 0; kt < 8; kt++) mma16816(acc, af[kt], bfr[kt]);
        int r0 = mt*16 + (lane >> 2);
        int c0 = n0 + (lane & 3)*2;
        float2 xv0 = *(const float2*)(x + (P0 + r0)*64 + c0);
        float2 xv1 = *(const float2*)(x + (P0 + r0 + 8)*64 + c0);
        float2 o0, o1;
        o0.x = fmaf(acc[0] + sB2[c0],   sBeta[c0],   xv0.x);
        o0.y = fmaf(acc[1] + sB2[c0+1], sBeta[c0+1], xv0.y);
        o1.x = fmaf(acc[2] + sB2[c0],   sBeta[c0],   xv1.x);
        o1.y = fmaf(acc[3] + sB2[c0+1], sBeta[c0+1], xv1.y);
        *(float2*)(g_x2 + (P0 + r0)*64 + c0)     = o0;
        *(float2*)(g_x2 + (P0 + r0 + 8)*64 + c0) = o1;
    }
}

// ---------------------------------------------------------------------------
// K4b1: LN2 -> pw3 (64 -> 256, interleaved) -> SimpleGate -> g_yb. mma.sync.
// ---------------------------------------------------------------------------
#define K4B1_SW_OFF  18432
#define K4B1_PAR_OFF 55296
#define K4B1_SMEM    56832

__global__ void __launch_bounds__(256) k4b1_ln_pw3(
    const float* __restrict__ b3v, const float* __restrict__ g2, const float* __restrict__ bb2)
{
    extern __shared__ char smem[];
    uint32_t sb = smem_u32(smem);
    int tid = threadIdx.x, wid = tid >> 5, lane = tid & 31;
    float* sB3 = (float*)(smem + K4B1_PAR_OFF);   // 256 (interleaved)
    float* sG  = sB3 + 256;                       // 64
    float* sBe = sG + 64;                         // 64

    {
        const uint4* src = (const uint4*)(g_w3t + tid*64);
        uint4* dst = (uint4*)(smem + K4B1_SW_OFF + tid*144);
        #pragma unroll
        for (int q = 0; q < 8; q++) dst[q] = src[q];
    }
    sB3[tid] = b3v[(tid & 1)*128 + (tid >> 1)];
    if (tid < 64){ sG[tid] = g2[tid]; sBe[tid] = bb2[tid]; }
    __syncthreads();

    size_t P0 = (size_t)blockIdx.x * 128;
    {   // LN2 of g_x2
        int px = tid >> 1, half = tid & 1;
        const float4* xp = (const float4*)(g_x2 + (P0 + px) * 64 + half * 32);
        float4 v[8];
        #pragma unroll
        for (int q = 0; q < 8; q++) v[q] = xp[q];
        float s = 0.f, ss = 0.f;
        #pragma unroll
        for (int q = 0; q < 8; q++){
            float4 t = v[q];
            s += t.x + t.y + t.z + t.w;
            ss = fmaf(t.x,t.x, fmaf(t.y,t.y, fmaf(t.z,t.z, fmaf(t.w,t.w, ss))));
        }
        s  += __shfl_xor_sync(0xffffffffu, s, 1);
        ss += __shfl_xor_sync(0xffffffffu, ss, 1);
        float mean = s * (1.f/64.f);
        float var  = fmaf(-mean, mean, ss * (1.f/64.f));
        float rstd = rsqrtf(var + EPSV);
        char* dstrow = smem + px*144 + half*64;
        #pragma unroll
        for (int g = 0; g < 4; g++){
            float4 va = v[2*g], vb = v[2*g+1];
            int c = half*32 + g*8;
            float f0 = fmaf((va.x-mean)*rstd, sG[c+0], sBe[c+0]);
            float f1 = fmaf((va.y-mean)*rstd, sG[c+1], sBe[c+1]);
            float f2 = fmaf((va.z-mean)*rstd, sG[c+2], sBe[c+2]);
            float f3 = fmaf((va.w-mean)*rstd, sG[c+3], sBe[c+3]);
            float f4 = fmaf((vb.x-mean)*rstd, sG[c+4], sBe[c+4]);
            float f5 = fmaf((vb.y-mean)*rstd, sG[c+5], sBe[c+5]);
            float f6 = fmaf((vb.z-mean)*rstd, sG[c+6], sBe[c+6]);
            float f7 = fmaf((vb.w-mean)*rstd, sG[c+7], sBe[c+7]);
            *(uint4*)(dstrow + g*16) = make_uint4(bfpack(f0,f1), bfpack(f2,f3),
                                                  bfpack(f4,f5), bfpack(f6,f7));
        }
    }
    __syncthreads();

    int ns = wid * 32;
    int br = lane & 7, bg = (lane >> 3) & 1;
    uint32_t bfr[4][4][2];
    #pragma unroll
    for (int nt = 0; nt < 4; nt++)
        #pragma unroll
        for (int kt = 0; kt < 4; kt++)
            ldsm2(bfr[nt][kt], sb + K4B1_SW_OFF + (ns + nt*8 + br)*144 + bg*16 + kt*32);

    int ag = lane >> 3, ar = lane & 7;
    uint32_t abase = sb + (ar + (ag & 1)*8)*144 + (ag >> 1)*16;
    #pragma unroll 1
    for (int mt = 0; mt < 8; mt++){
        uint32_t af[4][4];
        #pragma unroll
        for (int kt = 0; kt < 4; kt++) ldsm4(af[kt], abase + mt*2304 + kt*32);
        float acc[4][4];
        #pragma unroll
        for (int nt = 0; nt < 4; nt++){ acc[nt][0]=0.f; acc[nt][1]=0.f; acc[nt][2]=0.f; acc[nt][3]=0.f; }
        #pragma unroll
        for (int kt = 0; kt < 4; kt++)
            #pragma unroll
            for (int nt = 0; nt < 4; nt++)
                mma16816(acc[nt], af[kt], bfr[nt][kt]);
        // SimpleGate: adjacent interleaved cols multiply -> one bf16 per pair
        int r0 = mt*16 + (lane >> 2);
        int c0 = ns + (lane & 3)*2;
        __nv_bfloat16* o0 = g_yb + (P0 + r0)*128;
        __nv_bfloat16* o1 = o0 + 8*128;
        #pragma unroll
        for (int nt = 0; nt < 4; nt++){
            int c = c0 + nt*8;
            float ga = (acc[nt][0] + sB3[c]) * (acc[nt][1] + sB3[c+1]);
            float gb = (acc[nt][2] + sB3[c]) * (acc[nt][3] + sB3[c+1]);
            o0[c >> 1] = __float2bfloat16(ga);
            o1[c >> 1] = __float2bfloat16(gb);
        }
    }
}

// ---------------------------------------------------------------------------
// K4b2: pw4 (128 -> 64) -> out = x2 + .*gamma. mma.sync, warp n-slice 8.
// ---------------------------------------------------------------------------
#define K4B2_SW_OFF  34816
#define K4B2_PAR_OFF 52224
#define K4B2_SMEM    52736

__global__ void __launch_bounds__(256) k4b2_pw4(
    const float* __restrict__ b4v, const float* __restrict__ gamma, float* __restrict__ out)
{
    extern __shared__ char smem[];
    uint32_t sb = smem_u32(smem);
    int tid = threadIdx.x, wid = tid >> 5, lane = tid & 31;
    float* sB4 = (float*)(smem + K4B2_PAR_OFF);   // 64
    float* sGa = sB4 + 64;                        // 64

    {
        int row = tid >> 2, part = tid & 3;
        const uint4* src = (const uint4*)(g_w4t + row*128 + part*32);
        uint4* dst = (uint4*)(smem + K4B2_SW_OFF + row*272 + part*64);
        #pragma unroll
        for (int q = 0; q < 4; q++) dst[q] = src[q];
    }
    if (tid < 64) sB4[tid] = b4v[tid];
    else if (tid < 128) sGa[tid-64] = gamma[tid-64];
    __syncthreads();

    size_t P0 = (size_t)blockIdx.x * 128;
    {   // stage A = gate output (bf16, padded rows)
        int row = tid >> 1, half = tid & 1;
        const uint4* src = (const uint4*)(g_yb + (P0 + row)*128 + half*64);
        char* dstrow = smem + row*272 + half*128;
        #pragma unroll
        for (int q = 0; q < 8; q++) *(uint4*)(dstrow + q*16) = src[q];
    }
    __syncthreads();

    int n0 = wid * 8;
    int br = lane & 7, bg = (lane >> 3) & 1;
    uint32_t bfr[8][2];
    #pragma unroll
    for (int kt = 0; kt < 8; kt++)
        ldsm2(bfr[kt], sb + K4B2_SW_OFF + (n0 + br)*272 + bg*16 + kt*32);

    int ag = lane >> 3, ar = lane & 7;
    uint32_t abase = sb + (ar + (ag & 1)*8)*272 + (ag >> 1)*16;
    #pragma unroll 1
    for (int mt = 0; mt < 8; mt++){
        uint32_t af[8][4];
        #pragma unroll
        for (int kt = 0; kt < 8; kt++) ldsm4(af[kt], abase + mt*4352 + kt*32);
        float acc[4] = {0.f, 0.f, 0.f, 0.f};
        #pragma unroll
        for (int kt = 0; kt < 8; kt++) mma16816(acc, af[kt], bfr[kt]);
        int r0 = mt*16 + (lane >> 2);
        int c0 = n0 + (lane & 3)*2;
        float2 xv0 = *(const float2*)(g_x2 + (P0 + r0)*64 + c0);
        float2 xv1 = *(const float2*)(g_x2 + (P0 + r0 + 8)*64 + c0);
        float2 o0, o1;
        o0.x = fmaf(acc[0] + sB4[c0],   sGa[c0],   xv0.x);
        o0.y = fmaf(acc[1] + sB4[c0+1], sGa[c0+1], xv0.y);
        o1.x = fmaf(acc[2] + sB4[c0],   sGa[c0],   xv1.x);
        o1.y = fmaf(acc[3] + sB4[c0+1], sGa[c0+1], xv1.y);
        *(float2*)(out + (P0 + r0)*64 + c0)     = o0;
        *(float2*)(out + (P0 + r0 + 8)*64 + c0) = o1;
    }
}

// ---------------------------------------------------------------------------
extern "C" void kernel_launch(void* const* d_in, const int* in_sizes, int n_in,
                              void* d_out, int out_size)
{
    const float* x    = (const float*)d_in[0];
    const float* ln1g = (const float*)d_in[1];
    const float* ln1b = (const float*)d_in[2];
    const float* pw1w = (const float*)d_in[3];
    const float* pw1b = (const float*)d_in[4];
    const float* dww  = (const float*)d_in[5];
    const float* dwb  = (const float*)d_in[6];
    const float* scaw = (const float*)d_in[7];
    const float* scab = (const float*)d_in[8];
    const float* pw2w = (const float*)d_in[9];
    const float* pw2b = (const float*)d_in[10];
    const float* beta = (const float*)d_in[11];
    const float* ln2g = (const float*)d_in[12];
    const float* ln2b = (const float*)d_in[13];
    const float* pw3w = (const float*)d_in[14];
    const float* pw3b = (const float*)d_in[15];
    const float* pw4w = (const float*)d_in[16];
    const float* pw4b = (const float*)d_in[17];
    const float* gam  = (const float*)d_in[18];
    float* out = (float*)d_out;

    cudaFuncSetAttribute(k1_ln_pw1,   cudaFuncAttributeMaxDynamicSharedMemorySize, K1_SMEM);
    cudaFuncSetAttribute(k4a_att_pw2, cudaFuncAttributeMaxDynamicSharedMemorySize, K4A_SMEM);
    cudaFuncSetAttribute(k4b1_ln_pw3, cudaFuncAttributeMaxDynamicSharedMemorySize, K4B1_SMEM);
    cudaFuncSetAttribute(k4b2_pw4,    cudaFuncAttributeMaxDynamicSharedMemorySize, K4B2_SMEM);

    k0_prep    <<<192, 256>>>(pw1w, pw2w, pw3w, pw4w);
    k1_ln_pw1  <<<NPIX/128, 256, K1_SMEM>>>(x, ln1g, ln1b, pw1b);
    k2_dw_gate <<<BB*512, 128>>>(dww, dwb);
    k3_sca     <<<BB, 128>>>(scaw, scab);
    k4a_att_pw2<<<NPIX/128, 256, K4A_SMEM>>>(x, pw2b, beta);
    k4b1_ln_pw3<<<NPIX/128, 256, K4B1_SMEM>>>(pw3b, ln2g, ln2b);
    k4b2_pw4   <<<NPIX/128, 256, K4B2_SMEM>>>(pw4b, gam, out);
}

// round 11
// speedup vs baseline: 2.1372x; 1.1880x over previous
#include <cuda_runtime.h>
#include <cuda_bf16.h>
#include <cstdint>

#define EPSV 1e-6f

#define BB 8
#define HH 256
#define WW 256
#define CC 64
#define NPIX (BB*HH*WW)

// ---------------------------------------------------------------------------
// Scratch (static __device__ globals per harness rules)
// ---------------------------------------------------------------------------
__device__ __nv_bfloat16 g_t1b[(size_t)NPIX * 256];  // pw1 output (bf16)
__device__ __nv_bfloat16 g_yb [(size_t)NPIX * 128];  // gated dw out (bf16)
__device__ float g_x2[(size_t)NPIX * CC];            // stage-1 residual (fp32)
__device__ float g_part[BB * 1024 * 128];            // GAP partials
__device__ float g_part2[128 * 128];                 // GAP stage-2 partials
__device__ float g_attn[BB * 128];                   // channel attention
// Transposed bf16 weights (n-major rows, k contiguous)
__device__ __align__(16) __nv_bfloat16 g_w1t[256*64];
__device__ __align__(16) __nv_bfloat16 g_w2t[64*128];
__device__ __align__(16) __nv_bfloat16 g_w3t[256*64];   // gate-interleaved rows
__device__ __align__(16) __nv_bfloat16 g_w4t[64*128];

// ---------------------------------------------------------------------------
// Helpers
// ---------------------------------------------------------------------------
__device__ __forceinline__ uint32_t smem_u32(const void* p){
    uint32_t a; asm("{ .reg .u64 t; cvta.to.shared.u64 t, %1; cvt.u32.u64 %0, t; }" : "=r"(a) : "l"(p)); return a;
}
__device__ __forceinline__ void ldsm4(uint32_t* r, uint32_t addr){
    asm volatile("ldmatrix.sync.aligned.m8n8.x4.shared.b16 {%0,%1,%2,%3}, [%4];"
        : "=r"(r[0]), "=r"(r[1]), "=r"(r[2]), "=r"(r[3]) : "r"(addr));
}
__device__ __forceinline__ void ldsm2(uint32_t* r, uint32_t addr){
    asm volatile("ldmatrix.sync.aligned.m8n8.x2.shared.b16 {%0,%1}, [%2];"
        : "=r"(r[0]), "=r"(r[1]) : "r"(addr));
}
__device__ __forceinline__ void mma16816(float* d, const uint32_t* a, const uint32_t* b){
    asm volatile("mma.sync.aligned.m16n8k16.row.col.f32.bf16.bf16.f32 "
        "{%0,%1,%2,%3}, {%4,%5,%6,%7}, {%8,%9}, {%0,%1,%2,%3};"
        : "+f"(d[0]), "+f"(d[1]), "+f"(d[2]), "+f"(d[3])
        : "r"(a[0]), "r"(a[1]), "r"(a[2]), "r"(a[3]), "r"(b[0]), "r"(b[1]));
}
__device__ __forceinline__ uint32_t bfpack(float a, float b){
    __nv_bfloat162 h = __floats2bfloat162_rn(a, b);
    return *(uint32_t*)&h;
}
__device__ __forceinline__ float2 bfunpk(uint32_t u){
    __nv_bfloat162 h = *(__nv_bfloat162*)&u;
    return __bfloat1622float2(h);
}
__device__ __forceinline__ void st_bf2(__nv_bfloat16* p, float a, float b){
    *(__nv_bfloat162*)p = __floats2bfloat162_rn(a, b);
}

// ---------------------------------------------------------------------------
// K0: weight prep — transposed bf16 (n-major)
// ---------------------------------------------------------------------------
__global__ void k0_prep(const float* __restrict__ w1, const float* __restrict__ w2,
                        const float* __restrict__ w3, const float* __restrict__ w4)
{
    int idx = blockIdx.x * 256 + threadIdx.x;     // 192*256 = 49152
    if (idx < 16384){                             // w1t [256 n][64 k]
        int n = idx >> 6, k = idx & 63;
        g_w1t[n*64 + k] = __float2bfloat16(w1[k*256 + n]);
    } else if (idx < 24576){                      // w2t [64 n][128 k]
        int i = idx - 16384; int n = i >> 7, k = i & 127;
        g_w2t[n*128 + k] = __float2bfloat16(w2[k*64 + n]);
    } else if (idx < 40960){                      // w3t interleaved [256 n][64 k]
        int i = idx - 24576; int n = i >> 6, k = i & 63;
        g_w3t[n*64 + k] = __float2bfloat16(w3[k*256 + (n & 1)*128 + (n >> 1)]);
    } else {                                      // w4t [64 n][128 k]
        int i = idx - 40960; int n = i >> 7, k = i & 127;
        g_w4t[n*128 + k] = __float2bfloat16(w4[k*64 + n]);
    }
}

// ---------------------------------------------------------------------------
// K1: LN1 + pw1 (64 -> 256) via mma.sync. 128 px/block, 256 threads (8 warps).
// ---------------------------------------------------------------------------
#define K1_SW_OFF   18432
#define K1_PAR_OFF  55296
#define K1_SMEM     56832

__global__ void __launch_bounds__(256) k1_ln_pw1(
    const float* __restrict__ x, const float* __restrict__ g1,
    const float* __restrict__ b1v, const float* __restrict__ bias)
{
    extern __shared__ char smem[];
    uint32_t sb = smem_u32(smem);
    int tid = threadIdx.x, wid = tid >> 5, lane = tid & 31;
    float* sBias = (float*)(smem + K1_PAR_OFF);   // 256
    float* sG  = sBias + 256;                     // 64
    float* sBe = sG + 64;                         // 64

    {
        const uint4* src = (const uint4*)(g_w1t + tid*64);
        uint4* dst = (uint4*)(smem + K1_SW_OFF + tid*144);
        #pragma unroll
        for (int q = 0; q < 8; q++) dst[q] = src[q];
    }
    sBias[tid] = bias[tid];
    if (tid < 64){ sG[tid] = g1[tid]; sBe[tid] = b1v[tid]; }
    __syncthreads();

    size_t P0 = (size_t)blockIdx.x * 128;
    {   // LN: 2 threads per pixel
        int px = tid >> 1, half = tid & 1;
        const float4* xp = (const float4*)(x + (P0 + px) * 64 + half * 32);
        float4 v[8];
        #pragma unroll
        for (int q = 0; q < 8; q++) v[q] = xp[q];
        float s = 0.f, ss = 0.f;
        #pragma unroll
        for (int q = 0; q < 8; q++){
            float4 t = v[q];
            s += t.x + t.y + t.z + t.w;
            ss = fmaf(t.x,t.x, fmaf(t.y,t.y, fmaf(t.z,t.z, fmaf(t.w,t.w, ss))));
        }
        s  += __shfl_xor_sync(0xffffffffu, s, 1);
        ss += __shfl_xor_sync(0xffffffffu, ss, 1);
        float mean = s * (1.f/64.f);
        float var  = fmaf(-mean, mean, ss * (1.f/64.f));
        float rstd = rsqrtf(var + EPSV);
        char* dstrow = smem + px*144 + half*64;
        #pragma unroll
        for (int g = 0; g < 4; g++){
            float4 va = v[2*g], vb = v[2*g+1];
            int c = half*32 + g*8;
            float f0 = fmaf((va.x-mean)*rstd, sG[c+0], sBe[c+0]);
            float f1 = fmaf((va.y-mean)*rstd, sG[c+1], sBe[c+1]);
            float f2 = fmaf((va.z-mean)*rstd, sG[c+2], sBe[c+2]);
            float f3 = fmaf((va.w-mean)*rstd, sG[c+3], sBe[c+3]);
            float f4 = fmaf((vb.x-mean)*rstd, sG[c+4], sBe[c+4]);
            float f5 = fmaf((vb.y-mean)*rstd, sG[c+5], sBe[c+5]);
            float f6 = fmaf((vb.z-mean)*rstd, sG[c+6], sBe[c+6]);
            float f7 = fmaf((vb.w-mean)*rstd, sG[c+7], sBe[c+7]);
            *(uint4*)(dstrow + g*16) = make_uint4(bfpack(f0,f1), bfpack(f2,f3),
                                                  bfpack(f4,f5), bfpack(f6,f7));
        }
    }
    __syncthreads();

    int ns = wid * 32;
    int br = lane & 7, bg = (lane >> 3) & 1;
    uint32_t bfr[4][4][2];
    #pragma unroll
    for (int nt = 0; nt < 4; nt++)
        #pragma unroll
        for (int kt = 0; kt < 4; kt++)
            ldsm2(bfr[nt][kt], sb + K1_SW_OFF + (ns + nt*8 + br)*144 + bg*16 + kt*32);

    int ag = lane >> 3, ar = lane & 7;
    uint32_t abase = sb + (ar + (ag & 1)*8)*144 + (ag >> 1)*16;
    #pragma unroll 1
    for (int mt = 0; mt < 8; mt++){
        uint32_t af[4][4];
        #pragma unroll
        for (int kt = 0; kt < 4; kt++) ldsm4(af[kt], abase + mt*2304 + kt*32);
        float acc[4][4];
        #pragma unroll
        for (int nt = 0; nt < 4; nt++){ acc[nt][0]=0.f; acc[nt][1]=0.f; acc[nt][2]=0.f; acc[nt][3]=0.f; }
        #pragma unroll
        for (int kt = 0; kt < 4; kt++)
            #pragma unroll
            for (int nt = 0; nt < 4; nt++)
                mma16816(acc[nt], af[kt], bfr[nt][kt]);
        int r0 = mt*16 + (lane >> 2);
        int c0 = ns + (lane & 3)*2;
        __nv_bfloat16* o0 = g_t1b + (P0 + r0)*256;
        __nv_bfloat16* o1 = o0 + 8*256;
        #pragma unroll
        for (int nt = 0; nt < 4; nt++){
            int c = c0 + nt*8;
            st_bf2(o0 + c, acc[nt][0] + sBias[c], acc[nt][1] + sBias[c+1]);
            st_bf2(o1 + c, acc[nt][2] + sBias[c], acc[nt][3] + sBias[c+1]);
        }
    }
}

// ---------------------------------------------------------------------------
// K2: depthwise 3x3 + SimpleGate + GAP partials (bf16 I/O)
// ---------------------------------------------------------------------------
__global__ void __launch_bounds__(128) k2_dw_gate(const float* __restrict__ dww, const float* __restrict__ dwb)
{
    int blk = blockIdx.x;            // b*512 + h*2 + wseg
    int b   = blk >> 9;
    int rem = blk & 511;
    int h   = rem >> 1;
    int wseg= rem & 1;
    int sub = threadIdx.x >> 6;
    int c2  = threadIdx.x & 63;
    int ch  = c2 * 2;
    int w0  = wseg*128 + sub*64;

    float2 wt0[9], wt1[9];
    #pragma unroll
    for (int i = 0; i < 9; i++){
        wt0[i] = make_float2(dww[i*256 + ch],       dww[i*256 + ch + 1]);
        wt1[i] = make_float2(dww[i*256 + 128 + ch], dww[i*256 + 128 + ch + 1]);
    }
    float2 bc0 = make_float2(dwb[ch], dwb[ch+1]);
    float2 bc1 = make_float2(dwb[128+ch], dwb[128+ch+1]);

    const __nv_bfloat162* img = (const __nv_bfloat162*)g_t1b;
    size_t rowb = (size_t)(b*256 + h) * 256;
    bool v0 = (h > 0), v2 = (h < HH-1);
    #define LD0(rr, wc) __bfloat1622float2(img[((rr) + (size_t)(wc))*128 + c2])
    #define LD1(rr, wc) __bfloat1622float2(img[((rr) + (size_t)(wc))*128 + 64 + c2])
    size_t r0 = rowb - 256, r1 = rowb, r2 = rowb + 256;
    const float2 Z = make_float2(0.f, 0.f);

    float2 win0[9], win1[9];
    {
        int wm = w0 - 1; bool vm = (wm >= 0);
        win0[0] = (v0 && vm) ? LD0(r0, wm) : Z;
        win0[3] =  vm        ? LD0(r1, wm) : Z;
        win0[6] = (v2 && vm) ? LD0(r2, wm) : Z;
        win1[0] = (v0 && vm) ? LD1(r0, wm) : Z;
        win1[3] =  vm        ? LD1(r1, wm) : Z;
        win1[6] = (v2 && vm) ? LD1(r2, wm) : Z;
        win0[1] = v0 ? LD0(r0, w0) : Z;
        win0[4] =      LD0(r1, w0);
        win0[7] = v2 ? LD0(r2, w0) : Z;
        win1[1] = v0 ? LD1(r0, w0) : Z;
        win1[4] =      LD1(r1, w0);
        win1[7] = v2 ? LD1(r2, w0) : Z;
    }
    __nv_bfloat162* yrow = (__nv_bfloat162*)g_yb;
    float2 gap = Z;
    for (int w = w0; w < w0 + 64; w++){
        int wp = w + 1; bool vp = (wp < WW);
        win0[2] = (v0 && vp) ? LD0(r0, wp) : Z;
        win0[5] =  vp        ? LD0(r1, wp) : Z;
        win0[8] = (v2 && vp) ? LD0(r2, wp) : Z;
        win1[2] = (v0 && vp) ? LD1(r0, wp) : Z;
        win1[5] =  vp        ? LD1(r1, wp) : Z;
        win1[8] = (v2 && vp) ? LD1(r2, wp) : Z;
        float2 a = bc0, c = bc1;
        #pragma unroll
        for (int i = 0; i < 9; i++){
            a.x = fmaf(win0[i].x, wt0[i].x, a.x); a.y = fmaf(win0[i].y, wt0[i].y, a.y);
            c.x = fmaf(win1[i].x, wt1[i].x, c.x); c.y = fmaf(win1[i].y, wt1[i].y, c.y);
        }
        float2 yv = make_float2(a.x * c.x, a.y * c.y);
        yrow[(rowb + (size_t)w)*64 + c2] = __floats2bfloat162_rn(yv.x, yv.y);
        gap.x += yv.x; gap.y += yv.y;
        #pragma unroll
        for (int r = 0; r < 3; r++){
            win0[r*3+0] = win0[r*3+1]; win0[r*3+1] = win0[r*3+2];
            win1[r*3+0] = win1[r*3+1]; win1[r*3+1] = win1[r*3+2];
        }
    }
    int pid = blk*2 + sub;
    g_part[(size_t)pid*128 + ch]     = gap.x;
    g_part[(size_t)pid*128 + ch + 1] = gap.y;
    #undef LD0
    #undef LD1
}

// ---------------------------------------------------------------------------
// K3a: GAP partial reduce (128 blocks x 128 threads, 64 rows each)
// ---------------------------------------------------------------------------
__global__ void __launch_bounds__(128) k3a_reduce()
{
    int blk = blockIdx.x;                 // b = blk>>4, chunk = blk&15
    int c = threadIdx.x;
    const float* p = g_part + ((size_t)(blk >> 4) * 1024 + (size_t)(blk & 15) * 64) * 128 + c;
    float s = 0.f;
    #pragma unroll 16
    for (int i = 0; i < 64; i++) s += p[(size_t)i * 128];
    g_part2[blk*128 + c] = s;
}

// ---------------------------------------------------------------------------
// K3b: final GAP reduce + SCA
// ---------------------------------------------------------------------------
__global__ void k3b_sca(const float* __restrict__ scaw, const float* __restrict__ scab)
{
    __shared__ float smn[128];
    int b = blockIdx.x, c = threadIdx.x;
    float s = 0.f;
    #pragma unroll
    for (int i = 0; i < 16; i++) s += g_part2[(b*16 + i)*128 + c];
    smn[c] = s * (1.f / 65536.f);
    __syncthreads();
    float a = scab[c];
    #pragma unroll 8
    for (int k = 0; k < 128; k++) a = fmaf(smn[k], scaw[k*128 + c], a);
    g_attn[b*128 + c] = a;
}

// ---------------------------------------------------------------------------
// K4a: (y*attn) -> pw2 (128 -> 64) -> x2 = x + .*beta. mma.sync, warp n-slice 8.
// ---------------------------------------------------------------------------
#define K4A_SW_OFF  34816
#define K4A_PAR_OFF 52224
#define K4A_SMEM    53248

__global__ void __launch_bounds__(256) k4a_att_pw2(
    const float* __restrict__ x, const float* __restrict__ b2v, const float* __restrict__ beta)
{
    extern __shared__ char smem[];
    uint32_t sb = smem_u32(smem);
    int tid = threadIdx.x, wid = tid >> 5, lane = tid & 31;
    float* sAttn = (float*)(smem + K4A_PAR_OFF);  // 128
    float* sB2   = sAttn + 128;                   // 64
    float* sBeta = sB2 + 64;                      // 64
    int b = blockIdx.x >> 9;

    {
        int row = tid >> 2, part = tid & 3;
        const uint4* src = (const uint4*)(g_w2t + row*128 + part*32);
        uint4* dst = (uint4*)(smem + K4A_SW_OFF + row*272 + part*64);
        #pragma unroll
        for (int q = 0; q < 4; q++) dst[q] = src[q];
    }
    if (tid < 128) sAttn[tid] = g_attn[b*128 + tid];
    else if (tid < 192) sB2[tid-128] = b2v[tid-128];
    else sBeta[tid-192] = beta[tid-192];
    __syncthreads();

    size_t P0 = (size_t)blockIdx.x * 128;
    {   // stage A = y * attn (bf16, padded rows)
        int row = tid >> 1, half = tid & 1;
        const uint4* src = (const uint4*)(g_yb + (P0 + row)*128 + half*64);
        char* dstrow = smem + row*272 + half*128;
        #pragma unroll
        for (int q = 0; q < 8; q++){
            uint4 raw = src[q];
            const uint32_t* rw = (const uint32_t*)&raw;
            int k0 = half*64 + q*8;
            uint32_t pk[4];
            #pragma unroll
            for (int j = 0; j < 4; j++){
                float2 f = bfunpk(rw[j]);
                f.x *= sAttn[k0 + 2*j]; f.y *= sAttn[k0 + 2*j + 1];
                pk[j] = bfpack(f.x, f.y);
            }
            *(uint4*)(dstrow + q*16) = make_uint4(pk[0], pk[1], pk[2], pk[3]);
        }
    }
    __syncthreads();

    int n0 = wid * 8;
    int br = lane & 7, bg = (lane >> 3) & 1;
    uint32_t bfr[8][2];
    #pragma unroll
    for (int kt = 0; kt < 8; kt++)
        ldsm2(bfr[kt], sb + K4A_SW_OFF + (n0 + br)*272 + bg*16 + kt*32);

    int ag = lane >> 3, ar = lane & 7;
    uint32_t abase = sb + (ar + (ag & 1)*8)*272 + (ag >> 1)*16;
    #pragma unroll 1
    for (int mt = 0; mt < 8; mt++){
        uint32_t af[8][4];
        #pragma unroll
        for (int kt = 0; kt < 8; kt++) ldsm4(af[kt], abase + mt*4352 + kt*32);
        float acc[4] = {0.f, 0.f, 0.f, 0.f};
        #pragma unroll
        for (int kt = 0; kt < 8; kt++) mma16816(acc, af[kt], bfr[kt]);
        int r0 = mt*16 + (lane >> 2);
        int c0 = n0 + (lane & 3)*2;
        float2 xv0 = *(const float2*)(x + (P0 + r0)*64 + c0);
        float2 xv1 = *(const float2*)(x + (P0 + r0 + 8)*64 + c0);
        float2 o0, o1;
        o0.x = fmaf(acc[0] + sB2[c0],   sBeta[c0],   xv0.x);
        o0.y = fmaf(acc[1] + sB2[c0+1], sBeta[c0+1], xv0.y);
        o1.x = fmaf(acc[2] + sB2[c0],   sBeta[c0],   xv1.x);
        o1.y = fmaf(acc[3] + sB2[c0+1], sBeta[c0+1], xv1.y);
        *(float2*)(g_x2 + (P0 + r0)*64 + c0)     = o0;
        *(float2*)(g_x2 + (P0 + r0 + 8)*64 + c0) = o1;
    }
}

// ---------------------------------------------------------------------------
// K4b (fused k4b1+k4b2): LN2 -> pw3 -> SimpleGate (smem) -> pw4 -> out.
// smem layout:
//   0      : A tile, LN2 out bf16 [128 x 144B]          (18432)
//   18432  : w3 (interleaved) [256 x 144B]              (36864)
//   55296  : gate tile bf16 [128 x 272B]                (34816)
//   90112  : w4 [64 x 272B]                             (17408)
//   107520 : params (sB3 256, sG 64, sBe 64, sB4 64, sGa 64) = 2048
// total 109568 -> 2 blocks/SM
// ---------------------------------------------------------------------------
#define K4B_SW3_OFF  18432
#define K4B_GT_OFF   55296
#define K4B_SW4_OFF  90112
#define K4B_PAR_OFF  107520
#define K4B_SMEM     109568

__global__ void __launch_bounds__(256) k4b_fused(
    const float* __restrict__ b3v, const float* __restrict__ g2, const float* __restrict__ bb2,
    const float* __restrict__ b4v, const float* __restrict__ gamma, float* __restrict__ out)
{
    extern __shared__ char smem[];
    uint32_t sb = smem_u32(smem);
    int tid = threadIdx.x, wid = tid >> 5, lane = tid & 31;
    float* sB3 = (float*)(smem + K4B_PAR_OFF);    // 256 (interleaved)
    float* sG  = sB3 + 256;                       // 64
    float* sBe = sG + 64;                         // 64
    float* sB4 = sBe + 64;                        // 64
    float* sGa = sB4 + 64;                        // 64

    {   // w3: thread t copies row t (64 bf16)
        const uint4* src = (const uint4*)(g_w3t + tid*64);
        uint4* dst = (uint4*)(smem + K4B_SW3_OFF + tid*144);
        #pragma unroll
        for (int q = 0; q < 8; q++) dst[q] = src[q];
    }
    {   // w4: 4 threads per row, 64B each
        int row = tid >> 2, part = tid & 3;
        const uint4* src = (const uint4*)(g_w4t + row*128 + part*32);
        uint4* dst = (uint4*)(smem + K4B_SW4_OFF + row*272 + part*64);
        #pragma unroll
        for (int q = 0; q < 4; q++) dst[q] = src[q];
    }
    sB3[tid] = b3v[(tid & 1)*128 + (tid >> 1)];
    if (tid < 64){ sG[tid] = g2[tid]; sBe[tid] = bb2[tid]; }
    else if (tid < 128) sB4[tid-64] = b4v[tid-64];
    else if (tid < 192) sGa[tid-128] = gamma[tid-128];
    __syncthreads();

    size_t P0 = (size_t)blockIdx.x * 128;
    {   // LN2 of g_x2 -> A tile
        int px = tid >> 1, half = tid & 1;
        const float4* xp = (const float4*)(g_x2 + (P0 + px) * 64 + half * 32);
        float4 v[8];
        #pragma unroll
        for (int q = 0; q < 8; q++) v[q] = xp[q];
        float s = 0.f, ss = 0.f;
        #pragma unroll
        for (int q = 0; q < 8; q++){
            float4 t = v[q];
            s += t.x + t.y + t.z + t.w;
            ss = fmaf(t.x,t.x, fmaf(t.y,t.y, fmaf(t.z,t.z, fmaf(t.w,t.w, ss))));
        }
        s  += __shfl_xor_sync(0xffffffffu, s, 1);
        ss += __shfl_xor_sync(0xffffffffu, ss, 1);
        float mean = s * (1.f/64.f);
        float var  = fmaf(-mean, mean, ss * (1.f/64.f));
        float rstd = rsqrtf(var + EPSV);
        char* dstrow = smem + px*144 + half*64;
        #pragma unroll
        for (int g = 0; g < 4; g++){
            float4 va = v[2*g], vb = v[2*g+1];
            int c = half*32 + g*8;
            float f0 = fmaf((va.x-mean)*rstd, sG[c+0], sBe[c+0]);
            float f1 = fmaf((va.y-mean)*rstd, sG[c+1], sBe[c+1]);
            float f2 = fmaf((va.z-mean)*rstd, sG[c+2], sBe[c+2]);
            float f3 = fmaf((va.w-mean)*rstd, sG[c+3], sBe[c+3]);
            float f4 = fmaf((vb.x-mean)*rstd, sG[c+4], sBe[c+4]);
            float f5 = fmaf((vb.y-mean)*rstd, sG[c+5], sBe[c+5]);
            float f6 = fmaf((vb.z-mean)*rstd, sG[c+6], sBe[c+6]);
            float f7 = fmaf((vb.w-mean)*rstd, sG[c+7], sBe[c+7]);
            *(uint4*)(dstrow + g*16) = make_uint4(bfpack(f0,f1), bfpack(f2,f3),
                                                  bfpack(f4,f5), bfpack(f6,f7));
        }
    }
    __syncthreads();

    // ---- phase 1: pw3 GEMM (warp n-slice 32, interleaved) + gate -> smem ----
    {
        int ns = wid * 32;
        int br = lane & 7, bg = (lane >> 3) & 1;
        uint32_t bfr[4][4][2];
        #pragma unroll
        for (int nt = 0; nt < 4; nt++)
            #pragma unroll
            for (int kt = 0; kt < 4; kt++)
                ldsm2(bfr[nt][kt], sb + K4B_SW3_OFF + (ns + nt*8 + br)*144 + bg*16 + kt*32);

        int ag = lane >> 3, ar = lane & 7;
        uint32_t abase = sb + (ar + (ag & 1)*8)*144 + (ag >> 1)*16;
        #pragma unroll 1
        for (int mt = 0; mt < 8; mt++){
            uint32_t af[4][4];
            #pragma unroll
            for (int kt = 0; kt < 4; kt++) ldsm4(af[kt], abase + mt*2304 + kt*32);
            float acc[4][4];
            #pragma unroll
            for (int nt = 0; nt < 4; nt++){ acc[nt][0]=0.f; acc[nt][1]=0.f; acc[nt][2]=0.f; acc[nt][3]=0.f; }
            #pragma unroll
            for (int kt = 0; kt < 4; kt++)
                #pragma unroll
                for (int nt = 0; nt < 4; nt++)
                    mma16816(acc[nt], af[kt], bfr[nt][kt]);
            int r0 = mt*16 + (lane >> 2);
            int c0 = ns + (lane & 3)*2;
            char* g0 = smem + K4B_GT_OFF + r0*272;
            char* g1 = g0 + 8*272;
            #pragma unroll
            for (int nt = 0; nt < 4; nt++){
                int c = c0 + nt*8;
                float ga = (acc[nt][0] + sB3[c]) * (acc[nt][1] + sB3[c+1]);
                float gb = (acc[nt][2] + sB3[c]) * (acc[nt][3] + sB3[c+1]);
                *(__nv_bfloat16*)(g0 + (c >> 1)*2) = __float2bfloat16(ga);
                *(__nv_bfloat16*)(g1 + (c >> 1)*2) = __float2bfloat16(gb);
            }
        }
    }
    __syncthreads();

    // ---- phase 2: pw4 GEMM (warp n-slice 8) + gamma residual -> out ----
    {
        int n0 = wid * 8;
        int br = lane & 7, bg = (lane >> 3) & 1;
        uint32_t bfr[8][2];
        #pragma unroll
        for (int kt = 0; kt < 8; kt++)
            ldsm2(bfr[kt], sb + K4B_SW4_OFF + (n0 + br)*272 + bg*16 + kt*32);

        int ag = lane >> 3, ar = lane & 7;
        uint32_t abase = sb + K4B_GT_OFF + (ar + (ag & 1)*8)*272 + (ag >> 1)*16;
        #pragma unroll 1
        for (int mt = 0; mt < 8; mt++){
            uint32_t af[8][4];
            #pragma unroll
            for (int kt = 0; kt < 8; kt++) ldsm4(af[kt], abase + mt*4352 + kt*32);
            float acc[4] = {0.f, 0.f, 0.f, 0.f};
            #pragma unroll
            for (int kt = 0; kt < 8; kt++) mma16816(acc, af[kt], bfr[kt]);
            int r0 = mt*16 + (lane >> 2);
            int c0 = n0 + (lane & 3)*2;
            float2 xv0 = *(const float2*)(g_x2 + (P0 + r0)*64 + c0);
            float2 xv1 = *(const float2*)(g_x2 + (P0 + r0 + 8)*64 + c0);
            float2 o0, o1;
            o0.x = fmaf(acc[0] + sB4[c0],   sGa[c0],   xv0.x);
            o0.y = fmaf(acc[1] + sB4[c0+1], sGa[c0+1], xv0.y);
            o1.x = fmaf(acc[2] + sB4[c0],   sGa[c0],   xv1.x);
            o1.y = fmaf(acc[3] + sB4[c0+1], sGa[c0+1], xv1.y);
            *(float2*)(out + (P0 + r0)*64 + c0)     = o0;
            *(float2*)(out + (P0 + r0 + 8)*64 + c0) = o1;
        }
    }
}

// ---------------------------------------------------------------------------
extern "C" void kernel_launch(void* const* d_in, const int* in_sizes, int n_in,
                              void* d_out, int out_size)
{
    const float* x    = (const float*)d_in[0];
    const float* ln1g = (const float*)d_in[1];
    const float* ln1b = (const float*)d_in[2];
    const float* pw1w = (const float*)d_in[3];
    const float* pw1b = (const float*)d_in[4];
    const float* dww  = (const float*)d_in[5];
    const float* dwb  = (const float*)d_in[6];
    const float* scaw = (const float*)d_in[7];
    const float* scab = (const float*)d_in[8];
    const float* pw2w = (const float*)d_in[9];
    const float* pw2b = (const float*)d_in[10];
    const float* beta = (const float*)d_in[11];
    const float* ln2g = (const float*)d_in[12];
    const float* ln2b = (const float*)d_in[13];
    const float* pw3w = (const float*)d_in[14];
    const float* pw3b = (const float*)d_in[15];
    const float* pw4w = (const float*)d_in[16];
    const float* pw4b = (const float*)d_in[17];
    const float* gam  = (const float*)d_in[18];
    float* out = (float*)d_out;

    cudaFuncSetAttribute(k1_ln_pw1,   cudaFuncAttributeMaxDynamicSharedMemorySize, K1_SMEM);
    cudaFuncSetAttribute(k4a_att_pw2, cudaFuncAttributeMaxDynamicSharedMemorySize, K4A_SMEM);
    cudaFuncSetAttribute(k4b_fused,   cudaFuncAttributeMaxDynamicSharedMemorySize, K4B_SMEM);

    k0_prep    <<<192, 256>>>(pw1w, pw2w, pw3w, pw4w);
    k1_ln_pw1  <<<NPIX/128, 256, K1_SMEM>>>(x, ln1g, ln1b, pw1b);
    k2_dw_gate <<<BB*512, 128>>>(dww, dwb);
    k3a_reduce <<<128, 128>>>();
    k3b_sca    <<<BB, 128>>>(scaw, scab);
    k4a_att_pw2<<<NPIX/128, 256, K4A_SMEM>>>(x, pw2b, beta);
    k4b_fused  <<<NPIX/128, 256, K4B_SMEM>>>(pw3b, ln2g, ln2b, pw4b, gam, out);
}